// round 10
// baseline (speedup 1.0000x reference)
#include <cuda_runtime.h>
#include <math.h>
#include <stdint.h>

#define NN 4096
#define BB 256
#define G  4              // batches per cluster
#define W  64             // steps per block
#define NB (NN / W)       // 64 blocks
#define NSEQ 128          // 4 chain warps (one per batch)
#define NBULK 512         // 16 bulk warps
#define T (NSEQ + NBULK)  // 640 threads
#define NCTA 128          // 64 clusters x 2

// Scratch (static device globals: allocation-free rule)
__device__ float  g_maskT[(size_t)NN * NN]; // maskT[i*N + k] = mask[k*N + i]
__device__ float2 g_thrA[(size_t)BB * NN];  // {T, flip}: s=+1 iff (acc>=T)^flip

// dynamic shared layout (>48KB static limit -> attribute)
struct __align__(16) Smem {
    float2 sbuf[2][W][G];      // duplicated {s,s}
    float  dbase[4][G][W];     // diag acc base columns, mod-4 slots
    float2 thrS[2][G][W];      // {T, flip}
    float  ds[2][W][W];        // diag mask tile
    float  es[2][W][W];        // superdiag mask tile
    unsigned long long mbar;   // peer-publisher mbarrier (count 8)
};

// ---------------- XLA-matching sigmoid ----------------
__device__ __forceinline__ float xla_tanh(float x) {
    float ax = fabsf(x);
    if (ax < 0.0004f) return x;
    float xc = fminf(fmaxf(x, -7.90531110763549805f), 7.90531110763549805f);
    float x2 = xc * xc;
    float p = -2.76076847742355e-16f;
    p = fmaf(x2, p, 2.00018790482477e-13f);
    p = fmaf(x2, p, -8.60467152213735e-11f);
    p = fmaf(x2, p, 5.12229709037114e-08f);
    p = fmaf(x2, p, 1.48572235717979e-05f);
    p = fmaf(x2, p, 6.37261928875436e-04f);
    p = fmaf(x2, p, 4.89352455891786e-03f);
    p = xc * p;
    float q = fmaf(x2, 1.19825839466702e-06f, 1.18534705686654e-04f);
    q = fmaf(x2, q, 2.26843463243900e-03f);
    q = fmaf(x2, q, 4.89352518554385e-03f);
    return p / q;
}
__device__ __forceinline__ float xla_sigmoid(float x) {
    return fmaf(0.5f, xla_tanh(0.5f * x), 0.5f);
}

// ---------------- ordered-int float helpers ----------------
__device__ __forceinline__ unsigned f2o(float f) {
    unsigned b = __float_as_uint(f);
    return (b & 0x80000000u) ? ~b : (b | 0x80000000u);
}
__device__ __forceinline__ float o2f(unsigned o) {
    unsigned b = (o & 0x80000000u) ? (o & 0x7fffffffu) : ~o;
    return __uint_as_float(b);
}

// Per (b,i): xT = smallest fp32 x with u < sigmoid_xla(x); then acc-space
// threshold via the exact monotone predicate rn(w*acc) >= xT.
__global__ void thr_kernel(const float* __restrict__ u,
                           const float* __restrict__ weight) {
    int idx = blockIdx.x * blockDim.x + threadIdx.x;
    if (idx >= BB * NN) return;
    int i = idx & (NN - 1);
    float uu = u[idx];
    float w = weight[i];

    const float SHI = xla_sigmoid(17.0f);
    const float SLO = xla_sigmoid(-17.0f);
    float xT;
    if (!(uu < SHI)) {
        xT = INFINITY;
    } else if (uu < SLO) {
        xT = -INFINITY;
    } else {
        float x0 = logf(uu) - logf(1.0f - uu);
        x0 = fminf(fmaxf(x0, -17.0f), 17.0f);
        float s0 = xla_sigmoid(x0);
        float d0 = fmaxf(s0 * (1.0f - s0), 1e-12f);
        float x1 = x0 - (s0 - uu) / d0;
        x1 = fminf(fmaxf(x1, -17.0f), 17.0f);
        float del = fmaf(fabsf(x1), 4e-6f, 5e-7f);
        float lo = x1 - del, hi = x1 + del;
        float dl = del;
        while (uu < xla_sigmoid(lo)) {
            dl *= 4.0f; lo = x1 - dl;
            if (lo <= -17.0f) { lo = -17.0f; break; }
        }
        float dh = del;
        while (!(uu < xla_sigmoid(hi))) {
            dh *= 4.0f; hi = x1 + dh;
            if (hi >= 17.0f) { hi = 17.0f; break; }
        }
        unsigned ilo = f2o(lo), ihi = f2o(hi);
        while (ihi - ilo > 1u) {
            unsigned mid = ilo + ((ihi - ilo) >> 1);
            if (uu < xla_sigmoid(o2f(mid))) ihi = mid; else ilo = mid;
        }
        xT = o2f(ihi);
    }

    float Tv; unsigned flip = 0u;
    if (xT == -INFINITY) {
        Tv = -INFINITY;
    } else if (xT == INFINITY) {
        Tv = INFINITY;
    } else if (w > 0.0f) {
        unsigned lo = f2o(-INFINITY), hi = f2o(INFINITY);
        while (hi - lo > 1u) {
            unsigned mid = lo + ((hi - lo) >> 1);
            if (__fmul_rn(w, o2f(mid)) >= xT) hi = mid; else lo = mid;
        }
        Tv = o2f(hi);
    } else if (w < 0.0f) {
        unsigned lo = f2o(-INFINITY), hi = f2o(INFINITY);
        while (hi - lo > 1u) {
            unsigned mid = lo + ((hi - lo) >> 1);
            if (!(__fmul_rn(w, o2f(mid)) >= xT)) hi = mid; else lo = mid;
        }
        Tv = o2f(hi);
        flip = 0xffffffffu;
    } else {
        Tv = (0.0f >= xT) ? -INFINITY : INFINITY;
    }
    g_thrA[idx] = make_float2(Tv, __uint_as_float(flip));
}

// ---------------- mask transpose ----------------
__global__ void transpose_kernel(const float* __restrict__ mask) {
    __shared__ float tile[32][33];
    int x = blockIdx.x * 32 + threadIdx.x;
    int y0 = blockIdx.y * 32 + threadIdx.y;
#pragma unroll
    for (int j = 0; j < 32; j += 8)
        tile[threadIdx.y + j][threadIdx.x] = mask[(size_t)(y0 + j) * NN + x];
    __syncthreads();
    int x2 = blockIdx.y * 32 + threadIdx.x;
    int y2 = blockIdx.x * 32 + threadIdx.y;
#pragma unroll
    for (int j = 0; j < 32; j += 8)
        g_maskT[(size_t)(y2 + j) * NN + x2] = tile[threadIdx.x][threadIdx.y + j];
}

// nop: shifts ncu's fixed capture slot (-s 5 -c 1) onto hot_kernel
__global__ void nop_kernel() {}

// ---------------- cluster / ptx helpers ----------------
__device__ __forceinline__ unsigned smem_u32(const void* p) {
    unsigned r;
    asm("{ .reg .u64 t; cvta.to.shared.u64 t, %1; cvt.u32.u64 %0, t; }"
        : "=r"(r) : "l"(p));
    return r;
}
__device__ __forceinline__ void st_peer64(unsigned laddr, unsigned peer,
                                          unsigned long long v) {
    unsigned r;
    asm("mapa.shared::cluster.u32 %0, %1, %2;" : "=r"(r) : "r"(laddr), "r"(peer));
    asm volatile("st.shared::cluster.b64 [%0], %1;" :: "r"(r), "l"(v) : "memory");
}
__device__ __forceinline__ void cluster_arrive_() {
    asm volatile("barrier.cluster.arrive.aligned;" ::: "memory");
}
__device__ __forceinline__ void cluster_wait_() {
    asm volatile("barrier.cluster.wait.aligned;" ::: "memory");
}
__device__ __forceinline__ unsigned ctarank_() {
    unsigned r; asm("mov.u32 %0, %%cluster_ctarank;" : "=r"(r)); return r;
}
__device__ __forceinline__ void fma2_(unsigned long long& d,
                                      unsigned long long a,
                                      unsigned long long b) {
    asm("fma.rn.f32x2 %0, %1, %2, %0;" : "+l"(d) : "l"(a), "l"(b));
}
__device__ __forceinline__ unsigned selb_(unsigned r, unsigned mv, unsigned pv) {
    return (r & mv) | (~r & pv);   // one LOP3
}
__device__ __forceinline__ unsigned sgn_(float v) {
    return (unsigned)(__float_as_int(v) >> 31);
}
__device__ __forceinline__ void mbar_init_(unsigned addr, unsigned cnt) {
    asm volatile("mbarrier.init.shared.b64 [%0], %1;"
                 :: "r"(addr), "r"(cnt) : "memory");
}
__device__ __forceinline__ void mbar_arrive_peer_(unsigned laddr, unsigned peer) {
    unsigned r;
    asm("mapa.shared::cluster.u32 %0, %1, %2;" : "=r"(r) : "r"(laddr), "r"(peer));
    asm volatile("mbarrier.arrive.release.cluster.shared::cluster.b64 _, [%0];"
                 :: "r"(r) : "memory");
}
__device__ __forceinline__ void mbar_wait_parity_(unsigned addr, unsigned parity) {
    unsigned done;
    do {
        asm volatile(
            "{\n\t.reg .pred p;\n\t"
            "mbarrier.try_wait.parity.acquire.cluster.shared::cta.b64 p, [%1], %2;\n\t"
            "selp.b32 %0, 1, 0, p;\n\t}"
            : "=r"(done) : "r"(addr), "r"(parity) : "memory");
    } while (!done);
}

// ---------------- hot kernel: cluster-2 split-k, blocked W=64 ----------------
// 64 clusters x 2 CTAs. NO per-epoch cluster barrier: one __syncthreads per
// epoch for intra-CTA handoffs; the only cross-CTA dependency (64 diag-column
// bases, 512B) flows through st.shared::cluster + an 8-count mbarrier that
// ONLY the 4 chain warps wait on. dbase is mod-4 buffered against drift.
__global__ __launch_bounds__(T, 1) __cluster_dims__(2, 1, 1)
void hot_kernel(const float* __restrict__ weight, float* __restrict__ out)
{
    extern __shared__ __align__(16) unsigned char smem_raw[];
    Smem* sm = (Smem*)smem_raw;

    const int tid = threadIdx.x;
    const unsigned rank = ctarank_();
    const int bb = (blockIdx.x >> 1) * G;
    const int lane = tid & 31;

    // bulk chunk ownership: 128B-granular interleave between the 2 CTAs
    const int bt = tid - NSEQ;
    const int cg = (bt >> 3) * 16 + (int)rank * 8 + (bt & 7);
    const ulonglong2* mbase = (const ulonglong2*)g_maskT;  // NN/4 per row
    unsigned long long A[8];
    ulonglong2 b[8];
#pragma unroll
    for (int q = 0; q < 8; q++) A[q] = 0ull;

    // ---- preload block-0 state ----
    for (int idx = tid; idx < W * W; idx += T) {
        int r = idx >> 6, c = idx & 63;
        sm->ds[0][r][c] = __ldg(g_maskT + (size_t)r * NN + c);
    }
    for (int idx = tid; idx < 4 * G * W; idx += T)
        ((float*)sm->dbase)[idx] = 0.0f;
    if (tid == 0) mbar_init_(smem_u32(&sm->mbar), 8);
    if (tid < NSEQ) {
        int g = tid >> 5;
        sm->thrS[0][g][lane]      = __ldg(g_thrA + (size_t)(bb + g) * NN + lane);
        sm->thrS[0][g][lane + 32] = __ldg(g_thrA + (size_t)(bb + g) * NN + lane + 32);
    } else {
#pragma unroll
        for (int q = 0; q < 8; q++)
            b[q] = __ldg(mbase + (size_t)q * (NN / 4) + cg);
    }
    __syncthreads();
    cluster_arrive_();      // mbar init visible cluster-wide before any arrive
    cluster_wait_();

    for (int it = 0; it <= NB; ++it) {
        const int par = it & 1;
        __syncthreads();    // all intra-CTA handoffs (sbuf, ds/es, local dbase)

        if (tid < NSEQ) {
            if (it < NB) {
                // wait for peer dbase halves (published during epoch it-1)
                if (it >= 2) mbar_wait_parity_(smem_u32(&sm->mbar), it & 1);

                const int I = it * W;
                const int g = tid >> 5;
                float al = sm->dbase[it & 3][g][lane];
                float ah = sm->dbase[it & 3][g][lane + 32];
                if (it > 0) {
                    const int pj = par ^ 1;
#pragma unroll 8
                    for (int j = 0; j < W; j++) {
                        float s = sm->sbuf[pj][j][g].x;
                        al = fmaf(s, sm->es[par][j][lane], al);
                        ah = fmaf(s, sm->es[par][j][lane + 32], ah);
                    }
                }
                float2 tfl = sm->thrS[par][g][lane];
                float2 tfh = sm->thrS[par][g][lane + 32];
                const float tl = tfl.x, th = tfh.x;
                const unsigned fll = __float_as_uint(tfl.y);
                const unsigned flh = __float_as_uint(tfh.y);

                // ---- phase A: steps 0..31 on al; maintain ah in shadow ----
                unsigned mine = 0u, r;
                float aP, aM, dhp;
                unsigned mP, mM;
                {
                    unsigned mm0 = sgn_(al - tl) ^ fll;
                    mine = (lane == 0) ? mm0 : mine;
                    r = __shfl_sync(0xffffffffu, mm0, 0);
                    float d = sm->ds[par][0][lane];
                    aP = al + d; aM = al - d;
                    mP = sgn_(aP - tl) ^ fll; mM = sgn_(aM - tl) ^ fll;
                    dhp = sm->ds[par][0][lane + 32];
                }
#pragma unroll
                for (int j = 1; j < 32; j++) {
                    unsigned mm = selb_(r, mM, mP);
                    mine = (lane == j) ? mm : mine;
                    unsigned rn = __shfl_sync(0xffffffffu, mm, j);
                    // shadow: select al, fold step j-1 into ah, build j cands
                    al = __uint_as_float(selb_(r, __float_as_uint(aM),
                                                  __float_as_uint(aP)));
                    float hP = ah + dhp, hM = ah - dhp;
                    ah = __uint_as_float(selb_(r, __float_as_uint(hM),
                                                  __float_as_uint(hP)));
                    float d = sm->ds[par][j][lane];
                    aP = al + d; aM = al - d;
                    mP = sgn_(aP - tl) ^ fll; mM = sgn_(aM - tl) ^ fll;
                    dhp = sm->ds[par][j][lane + 32];
                    r = rn;
                }
                {   // apply step 31 to ah
                    float hP = ah + dhp, hM = ah - dhp;
                    ah = __uint_as_float(selb_(r, __float_as_uint(hM),
                                                  __float_as_uint(hP)));
                }
                float sA = __uint_as_float(0x3f800000u | (mine & 0x80000000u));
                sm->sbuf[par][lane][g] = make_float2(sA, sA);
                if (rank == 0) out[(size_t)(bb + g) * NN + I + lane] = sA;

                // ---- phase B: steps 32..63 on ah ----
                mine = 0u;
                {
                    unsigned mm0 = sgn_(ah - th) ^ flh;
                    mine = (lane == 0) ? mm0 : mine;
                    r = __shfl_sync(0xffffffffu, mm0, 0);
                    float d = sm->ds[par][32][lane + 32];
                    aP = ah + d; aM = ah - d;
                    mP = sgn_(aP - th) ^ flh; mM = sgn_(aM - th) ^ flh;
                }
#pragma unroll
                for (int j = 1; j < 32; j++) {
                    unsigned mm = selb_(r, mM, mP);
                    mine = (lane == j) ? mm : mine;
                    unsigned rn = __shfl_sync(0xffffffffu, mm, j);
                    ah = __uint_as_float(selb_(r, __float_as_uint(aM),
                                                  __float_as_uint(aP)));
                    float d = sm->ds[par][32 + j][lane + 32];
                    aP = ah + d; aM = ah - d;
                    mP = sgn_(aP - th) ^ flh; mM = sgn_(aM - th) ^ flh;
                    r = rn;
                }
                float sB = __uint_as_float(0x3f800000u | (mine & 0x80000000u));
                sm->sbuf[par][32 + lane][g] = make_float2(sB, sB);
                if (rank == 0) out[(size_t)(bb + g) * NN + I + 32 + lane] = sB;

                // stage thresholds for block it+1
                if (it + 1 < NB) {
                    const int I2 = (it + 1) * W;
                    sm->thrS[par ^ 1][g][lane] =
                        __ldg(g_thrA + (size_t)(bb + g) * NN + I2 + lane);
                    sm->thrS[par ^ 1][g][lane + 32] =
                        __ldg(g_thrA + (size_t)(bb + g) * NN + I2 + lane + 32);
                }
            }
        } else if (it == 0) {
            // stage ds/es for block 1 (ring already warm from prologue)
            const int I2 = W;
            for (int idx = bt; idx < W * W; idx += NBULK) {
                int rr = idx >> 6, cc = idx & 63;
                sm->ds[1][rr][cc] = __ldg(g_maskT + (size_t)(I2 + rr) * NN + I2 + cc);
                sm->es[1][rr][cc] = __ldg(g_maskT + (size_t)(rr) * NN + I2 + cc);
            }
        } else {
            // ---- bulk(it-1): rank-64 update on owned chunk, pipelined ----
            const int n = it - 1, I = n * W;
            if (4 * cg + 3 > I) {
                const int pj = n & 1;
                const bool an = (n + 1 < NB) && (4 * cg + 3 > I + W);
                const ulonglong2* sp = (const ulonglong2*)&sm->sbuf[pj][0][0];
                ulonglong2 sA = sp[0], sB = sp[1];    // s-prefetch ring
#pragma unroll 8
                for (int j = 0; j < W - 8; j++) {
                    ulonglong2 m2 = b[j & 7];
                    b[j & 7] = __ldg(mbase + (size_t)(I + j + 8) * (NN / 4) + cg);
                    ulonglong2 nA = sp[2 * j + 2];
                    ulonglong2 nB = sp[2 * j + 3];
                    fma2_(A[0], sA.x, m2.x); fma2_(A[1], sA.x, m2.y);
                    fma2_(A[2], sA.y, m2.x); fma2_(A[3], sA.y, m2.y);
                    fma2_(A[4], sB.x, m2.x); fma2_(A[5], sB.x, m2.y);
                    fma2_(A[6], sB.y, m2.x); fma2_(A[7], sB.y, m2.y);
                    sA = nA; sB = nB;
                }
#pragma unroll
                for (int j = W - 8; j < W; j++) {
                    ulonglong2 m2 = b[j & 7];
                    if (an)
                        b[j & 7] = __ldg(mbase +
                            (size_t)(I + W + (j - (W - 8))) * (NN / 4) + cg);
                    ulonglong2 nA, nB;
                    if (j < W - 1) { nA = sp[2 * j + 2]; nB = sp[2 * j + 3]; }
                    fma2_(A[0], sA.x, m2.x); fma2_(A[1], sA.x, m2.y);
                    fma2_(A[2], sA.y, m2.x); fma2_(A[3], sA.y, m2.y);
                    fma2_(A[4], sB.x, m2.x); fma2_(A[5], sB.x, m2.y);
                    fma2_(A[6], sB.y, m2.x); fma2_(A[7], sB.y, m2.y);
                    if (j < W - 1) { sA = nA; sB = nB; }
                }
            }
            // publish diag acc base for S(it+1): local slot + peer via DSMEM,
            // then ONE release-arrive on the peer's mbarrier (8 arrivals/epoch)
            if (it + 1 < NB) {
                const int cd0 = (it + 1) * 16;
                if (cg >= cd0 && cg < cd0 + 16) {
                    const int off = (cg - cd0) * 4;
                    const int sl = (it + 1) & 3;
#pragma unroll
                    for (int g = 0; g < G; g++) {
                        unsigned long long* dst =
                            (unsigned long long*)&sm->dbase[sl][g][off];
                        dst[0] = A[2 * g]; dst[1] = A[2 * g + 1];
                        unsigned la = smem_u32(dst);
                        st_peer64(la, rank ^ 1u, A[2 * g]);
                        st_peer64(la + 8, rank ^ 1u, A[2 * g + 1]);
                    }
                    mbar_arrive_peer_(smem_u32(&sm->mbar), rank ^ 1u);
                }
            }
            // stage ds/es tiles for block it+1
            if (it + 1 < NB) {
                const int I2 = (it + 1) * W;
                const int p2 = par ^ 1;
                for (int idx = bt; idx < W * W; idx += NBULK) {
                    int rr = idx >> 6, cc = idx & 63;
                    sm->ds[p2][rr][cc] =
                        __ldg(g_maskT + (size_t)(I2 + rr) * NN + I2 + cc);
                    sm->es[p2][rr][cc] =
                        __ldg(g_maskT + (size_t)(I2 - W + rr) * NN + I2 + cc);
                }
            }
        }
    }

    // ---- x_hat epilogue: row N-1 of maskT is all-zero, so A == acc_prev ----
    if (tid >= NSEQ) {
        float* xh = out + (size_t)BB * NN;
        float4 wv = __ldg((const float4*)weight + cg);
#pragma unroll
        for (int g = 0; g < G; g++) {
            float a0 = __uint_as_float((unsigned)(A[2 * g] & 0xffffffffu));
            float a1 = __uint_as_float((unsigned)(A[2 * g] >> 32));
            float a2 = __uint_as_float((unsigned)(A[2 * g + 1] & 0xffffffffu));
            float a3 = __uint_as_float((unsigned)(A[2 * g + 1] >> 32));
            float4 r;
            r.x = xla_sigmoid(__fmul_rn(wv.x, a0));
            r.y = xla_sigmoid(__fmul_rn(wv.y, a1));
            r.z = xla_sigmoid(__fmul_rn(wv.z, a2));
            r.w = xla_sigmoid(__fmul_rn(wv.w, a3));
            *(float4*)(xh + (size_t)(bb + g) * NN + 4 * cg) = r;
        }
    }
    __syncthreads();
    cluster_arrive_();   // no CTA exits while peer DSMEM traffic may be in flight
    cluster_wait_();
}

extern "C" void kernel_launch(void* const* d_in, const int* in_sizes, int n_in,
                              void* d_out, int out_size)
{
    const float* weight = (const float*)d_in[0]; // [N]
    const float* mask   = (const float*)d_in[1]; // [N,N] row-major
    const float* u      = (const float*)d_in[2]; // [B,N]
    float* out = (float*)d_out;                  // [2*B*N]: sample then x_hat

    // raise dynamic smem cap (not a stream op; capture-safe, idempotent)
    cudaFuncSetAttribute(hot_kernel,
                         cudaFuncAttributeMaxDynamicSharedMemorySize,
                         (int)sizeof(Smem));

    dim3 tb(32, 8), tg(NN / 32, NN / 32);
    transpose_kernel<<<tg, tb>>>(mask);
    thr_kernel<<<(BB * NN + 255) / 256, 256>>>(u, weight);
    nop_kernel<<<1, 32>>>();   // shifts ncu capture slot onto hot_kernel
    hot_kernel<<<NCTA, T, sizeof(Smem)>>>(weight, out);
    (void)in_sizes; (void)n_in; (void)out_size;
}

// round 11
// speedup vs baseline: 1.2518x; 1.2518x over previous
#include <cuda_runtime.h>
#include <math.h>
#include <stdint.h>

#define NN 4096
#define BB 256
#define G  4              // batches per cluster
#define W  64             // steps per block
#define NB (NN / W)       // 64 blocks
#define NSEQ 128          // 4 chain warps (one per batch)
#define NBULK 512         // 16 bulk warps
#define T (NSEQ + NBULK)  // 640 threads
#define NCTA 128          // 64 clusters x 2

// Scratch (static device globals: allocation-free rule)
__device__ float  g_maskT[(size_t)NN * NN]; // maskT[i*N + k] = mask[k*N + i]
__device__ float2 g_thrA[(size_t)BB * NN];  // {T, flip}: s=+1 iff (acc>=T)^flip

// dynamic shared layout (>48KB static limit -> attribute)
struct __align__(16) Smem {
    float4 sbuf4[2][W];     // s per row: {g0,g1,g2,g3} (not duplicated)
    float  dbase[2][G][W];  // diag acc base columns
    float2 thrS[2][G][W];   // {T, flip}
    float  ds[2][W][W];     // diag mask tile
    float  es[2][W][W];     // superdiag mask tile
};

// ---------------- XLA-matching sigmoid ----------------
__device__ __forceinline__ float xla_tanh(float x) {
    float ax = fabsf(x);
    if (ax < 0.0004f) return x;
    float xc = fminf(fmaxf(x, -7.90531110763549805f), 7.90531110763549805f);
    float x2 = xc * xc;
    float p = -2.76076847742355e-16f;
    p = fmaf(x2, p, 2.00018790482477e-13f);
    p = fmaf(x2, p, -8.60467152213735e-11f);
    p = fmaf(x2, p, 5.12229709037114e-08f);
    p = fmaf(x2, p, 1.48572235717979e-05f);
    p = fmaf(x2, p, 6.37261928875436e-04f);
    p = fmaf(x2, p, 4.89352455891786e-03f);
    p = xc * p;
    float q = fmaf(x2, 1.19825839466702e-06f, 1.18534705686654e-04f);
    q = fmaf(x2, q, 2.26843463243900e-03f);
    q = fmaf(x2, q, 4.89352518554385e-03f);
    return p / q;
}
__device__ __forceinline__ float xla_sigmoid(float x) {
    return fmaf(0.5f, xla_tanh(0.5f * x), 0.5f);
}

// ---------------- ordered-int float helpers ----------------
__device__ __forceinline__ unsigned f2o(float f) {
    unsigned b = __float_as_uint(f);
    return (b & 0x80000000u) ? ~b : (b | 0x80000000u);
}
__device__ __forceinline__ float o2f(unsigned o) {
    unsigned b = (o & 0x80000000u) ? (o & 0x7fffffffu) : ~o;
    return __uint_as_float(b);
}

// Per (b,i): xT = smallest fp32 x with u < sigmoid_xla(x); then acc-space
// threshold via the exact monotone predicate rn(w*acc) >= xT.
__global__ void thr_kernel(const float* __restrict__ u,
                           const float* __restrict__ weight) {
    int idx = blockIdx.x * blockDim.x + threadIdx.x;
    if (idx >= BB * NN) return;
    int i = idx & (NN - 1);
    float uu = u[idx];
    float w = weight[i];

    const float SHI = xla_sigmoid(17.0f);
    const float SLO = xla_sigmoid(-17.0f);
    float xT;
    if (!(uu < SHI)) {
        xT = INFINITY;
    } else if (uu < SLO) {
        xT = -INFINITY;
    } else {
        float x0 = logf(uu) - logf(1.0f - uu);
        x0 = fminf(fmaxf(x0, -17.0f), 17.0f);
        float s0 = xla_sigmoid(x0);
        float d0 = fmaxf(s0 * (1.0f - s0), 1e-12f);
        float x1 = x0 - (s0 - uu) / d0;
        x1 = fminf(fmaxf(x1, -17.0f), 17.0f);
        float del = fmaf(fabsf(x1), 4e-6f, 5e-7f);
        float lo = x1 - del, hi = x1 + del;
        float dl = del;
        while (uu < xla_sigmoid(lo)) {
            dl *= 4.0f; lo = x1 - dl;
            if (lo <= -17.0f) { lo = -17.0f; break; }
        }
        float dh = del;
        while (!(uu < xla_sigmoid(hi))) {
            dh *= 4.0f; hi = x1 + dh;
            if (hi >= 17.0f) { hi = 17.0f; break; }
        }
        unsigned ilo = f2o(lo), ihi = f2o(hi);
        while (ihi - ilo > 1u) {
            unsigned mid = ilo + ((ihi - ilo) >> 1);
            if (uu < xla_sigmoid(o2f(mid))) ihi = mid; else ilo = mid;
        }
        xT = o2f(ihi);
    }

    float Tv; unsigned flip = 0u;
    if (xT == -INFINITY) {
        Tv = -INFINITY;
    } else if (xT == INFINITY) {
        Tv = INFINITY;
    } else if (w > 0.0f) {
        unsigned lo = f2o(-INFINITY), hi = f2o(INFINITY);
        while (hi - lo > 1u) {
            unsigned mid = lo + ((hi - lo) >> 1);
            if (__fmul_rn(w, o2f(mid)) >= xT) hi = mid; else lo = mid;
        }
        Tv = o2f(hi);
    } else if (w < 0.0f) {
        unsigned lo = f2o(-INFINITY), hi = f2o(INFINITY);
        while (hi - lo > 1u) {
            unsigned mid = lo + ((hi - lo) >> 1);
            if (!(__fmul_rn(w, o2f(mid)) >= xT)) hi = mid; else lo = mid;
        }
        Tv = o2f(hi);
        flip = 0xffffffffu;
    } else {
        Tv = (0.0f >= xT) ? -INFINITY : INFINITY;
    }
    g_thrA[idx] = make_float2(Tv, __uint_as_float(flip));
}

// ---------------- mask transpose ----------------
__global__ void transpose_kernel(const float* __restrict__ mask) {
    __shared__ float tile[32][33];
    int x = blockIdx.x * 32 + threadIdx.x;
    int y0 = blockIdx.y * 32 + threadIdx.y;
#pragma unroll
    for (int j = 0; j < 32; j += 8)
        tile[threadIdx.y + j][threadIdx.x] = mask[(size_t)(y0 + j) * NN + x];
    __syncthreads();
    int x2 = blockIdx.y * 32 + threadIdx.x;
    int y2 = blockIdx.x * 32 + threadIdx.y;
#pragma unroll
    for (int j = 0; j < 32; j += 8)
        g_maskT[(size_t)(y2 + j) * NN + x2] = tile[threadIdx.x][threadIdx.y + j];
}

// nop: shifts ncu's fixed capture slot (-s 5 -c 1) onto hot_kernel
__global__ void nop_kernel() {}

// ---------------- cluster / ptx helpers ----------------
__device__ __forceinline__ unsigned smem_u32(const void* p) {
    unsigned r;
    asm("{ .reg .u64 t; cvta.to.shared.u64 t, %1; cvt.u32.u64 %0, t; }"
        : "=r"(r) : "l"(p));
    return r;
}
__device__ __forceinline__ void st_peer64(unsigned laddr, unsigned peer,
                                          unsigned long long v) {
    unsigned r;
    asm("mapa.shared::cluster.u32 %0, %1, %2;" : "=r"(r) : "r"(laddr), "r"(peer));
    asm volatile("st.shared::cluster.b64 [%0], %1;" :: "r"(r), "l"(v) : "memory");
}
__device__ __forceinline__ void cluster_arrive_() {
    asm volatile("barrier.cluster.arrive.aligned;" ::: "memory");
}
__device__ __forceinline__ void cluster_wait_() {
    asm volatile("barrier.cluster.wait.aligned;" ::: "memory");
}
__device__ __forceinline__ unsigned ctarank_() {
    unsigned r; asm("mov.u32 %0, %%cluster_ctarank;" : "=r"(r)); return r;
}
__device__ __forceinline__ void fma2_(unsigned long long& d,
                                      unsigned long long a,
                                      unsigned long long b) {
    asm("fma.rn.f32x2 %0, %1, %2, %0;" : "+l"(d) : "l"(a), "l"(b));
}
__device__ __forceinline__ unsigned long long dup_(float s) {
    unsigned long long r;
    asm("mov.b64 %0, {%1, %1};" : "=l"(r) : "f"(s));
    return r;
}
__device__ __forceinline__ unsigned selb_(unsigned r, unsigned mv, unsigned pv) {
    return (r & mv) | (~r & pv);   // one LOP3
}
__device__ __forceinline__ unsigned sgn_(float v) {
    return (unsigned)(__float_as_int(v) >> 31);
}

// ---------------- hot kernel: cluster-2 split-k, blocked W=64 ----------------
// 64 clusters x 2 CTAs. Per epoch: wait -> syncthreads -> work -> arrive ->
// vectorized stage (4 LDG.128 + 4 STS.128 per bulk thread; loads batched).
// Warps 0-3: 64-step chain as two 32-step speculative passes. 16 bulk warps:
// rank-64 f32x2 updates; 8-deep mask LDG ring; single float4 s-load per row
// with in-register duplication; one float4 column-slot per thread.
__global__ __launch_bounds__(T, 1) __cluster_dims__(2, 1, 1)
void hot_kernel(const float* __restrict__ weight, float* __restrict__ out)
{
    extern __shared__ __align__(16) unsigned char smem_raw[];
    Smem* sm = (Smem*)smem_raw;

    const int tid = threadIdx.x;
    const unsigned rank = ctarank_();
    const int bb = (blockIdx.x >> 1) * G;
    const int lane = tid & 31;

    // bulk chunk ownership: 128B-granular interleave between the 2 CTAs
    const int bt = tid - NSEQ;
    const int cg = (bt >> 3) * 16 + (int)rank * 8 + (bt & 7);
    const ulonglong2* mbase = (const ulonglong2*)g_maskT;  // NN/4 per row
    unsigned long long A[8];
    ulonglong2 b[8];
#pragma unroll
    for (int q = 0; q < 8; q++) A[q] = 0ull;

    // ---- preload block-0 state ----
    for (int idx = tid; idx < W * W; idx += T) {
        int r = idx >> 6, c = idx & 63;
        sm->ds[0][r][c] = __ldg(g_maskT + (size_t)r * NN + c);
    }
    for (int idx = tid; idx < 2 * G * W; idx += T)
        ((float*)sm->dbase)[idx] = 0.0f;
    if (tid < NSEQ) {
        int g = tid >> 5;
        sm->thrS[0][g][lane]      = __ldg(g_thrA + (size_t)(bb + g) * NN + lane);
        sm->thrS[0][g][lane + 32] = __ldg(g_thrA + (size_t)(bb + g) * NN + lane + 32);
    } else {
#pragma unroll
        for (int q = 0; q < 8; q++)
            b[q] = __ldg(mbase + (size_t)q * (NN / 4) + cg);
    }
    __syncthreads();
    cluster_arrive_();

    for (int it = 0; it <= NB; ++it) {
        const int par = it & 1;
        cluster_wait_();
        __syncthreads();

        if (tid < NSEQ) {
            if (it < NB) {
                const int I = it * W;
                const int g = tid >> 5;
                float al = sm->dbase[par][g][lane];
                float ah = sm->dbase[par][g][lane + 32];
                if (it > 0) {
                    const int pj = par ^ 1;
                    const float* sg = (const float*)&sm->sbuf4[pj][0] + g;
#pragma unroll 8
                    for (int j = 0; j < W; j++) {
                        float s = sg[4 * j];
                        al = fmaf(s, sm->es[par][j][lane], al);
                        ah = fmaf(s, sm->es[par][j][lane + 32], ah);
                    }
                }
                float2 tfl = sm->thrS[par][g][lane];
                float2 tfh = sm->thrS[par][g][lane + 32];
                const float tl = tfl.x, th = tfh.x;
                const unsigned fll = __float_as_uint(tfl.y);
                const unsigned flh = __float_as_uint(tfh.y);

                // ---- phase A: steps 0..31 on al; maintain ah in shadow ----
                unsigned mine = 0u, r;
                float aP, aM, dhp;
                unsigned mP, mM;
                {
                    unsigned mm0 = sgn_(al - tl) ^ fll;
                    mine = (lane == 0) ? mm0 : mine;
                    r = __shfl_sync(0xffffffffu, mm0, 0);
                    float d = sm->ds[par][0][lane];
                    aP = al + d; aM = al - d;
                    mP = sgn_(aP - tl) ^ fll; mM = sgn_(aM - tl) ^ fll;
                    dhp = sm->ds[par][0][lane + 32];
                }
#pragma unroll
                for (int j = 1; j < 32; j++) {
                    unsigned mm = selb_(r, mM, mP);
                    mine = (lane == j) ? mm : mine;
                    unsigned rn = __shfl_sync(0xffffffffu, mm, j);
                    // shadow: select al, fold step j-1 into ah, build j cands
                    al = __uint_as_float(selb_(r, __float_as_uint(aM),
                                                  __float_as_uint(aP)));
                    float hP = ah + dhp, hM = ah - dhp;
                    ah = __uint_as_float(selb_(r, __float_as_uint(hM),
                                                  __float_as_uint(hP)));
                    float d = sm->ds[par][j][lane];
                    aP = al + d; aM = al - d;
                    mP = sgn_(aP - tl) ^ fll; mM = sgn_(aM - tl) ^ fll;
                    dhp = sm->ds[par][j][lane + 32];
                    r = rn;
                }
                {   // apply step 31 to ah
                    float hP = ah + dhp, hM = ah - dhp;
                    ah = __uint_as_float(selb_(r, __float_as_uint(hM),
                                                  __float_as_uint(hP)));
                }
                float sA = __uint_as_float(0x3f800000u | (mine & 0x80000000u));
                ((float*)&sm->sbuf4[par][lane])[g] = sA;
                if (rank == 0) out[(size_t)(bb + g) * NN + I + lane] = sA;

                // ---- phase B: steps 32..63 on ah ----
                mine = 0u;
                {
                    unsigned mm0 = sgn_(ah - th) ^ flh;
                    mine = (lane == 0) ? mm0 : mine;
                    r = __shfl_sync(0xffffffffu, mm0, 0);
                    float d = sm->ds[par][32][lane + 32];
                    aP = ah + d; aM = ah - d;
                    mP = sgn_(aP - th) ^ flh; mM = sgn_(aM - th) ^ flh;
                }
#pragma unroll
                for (int j = 1; j < 32; j++) {
                    unsigned mm = selb_(r, mM, mP);
                    mine = (lane == j) ? mm : mine;
                    unsigned rn = __shfl_sync(0xffffffffu, mm, j);
                    ah = __uint_as_float(selb_(r, __float_as_uint(aM),
                                                  __float_as_uint(aP)));
                    float d = sm->ds[par][32 + j][lane + 32];
                    aP = ah + d; aM = ah - d;
                    mP = sgn_(aP - th) ^ flh; mM = sgn_(aM - th) ^ flh;
                    r = rn;
                }
                float sB = __uint_as_float(0x3f800000u | (mine & 0x80000000u));
                ((float*)&sm->sbuf4[par][32 + lane])[g] = sB;
                if (rank == 0) out[(size_t)(bb + g) * NN + I + 32 + lane] = sB;
            }
        } else if (it >= 1) {
            // ---- bulk(it-1): rank-64 update on owned chunk, pipelined ----
            const int n = it - 1, I = n * W;
            if (4 * cg + 3 > I) {
                const int pj = n & 1;
                const bool an = (n + 1 < NB) && (4 * cg + 3 > I + W);
                const float4* sp4 = &sm->sbuf4[pj][0];
                float4 sc = sp4[0];                    // s-prefetch ring
#pragma unroll 8
                for (int j = 0; j < W - 8; j++) {
                    ulonglong2 m2 = b[j & 7];
                    b[j & 7] = __ldg(mbase + (size_t)(I + j + 8) * (NN / 4) + cg);
                    float4 sn = sp4[j + 1];
                    unsigned long long s0 = dup_(sc.x), s1 = dup_(sc.y);
                    unsigned long long s2 = dup_(sc.z), s3 = dup_(sc.w);
                    fma2_(A[0], s0, m2.x); fma2_(A[1], s0, m2.y);
                    fma2_(A[2], s1, m2.x); fma2_(A[3], s1, m2.y);
                    fma2_(A[4], s2, m2.x); fma2_(A[5], s2, m2.y);
                    fma2_(A[6], s3, m2.x); fma2_(A[7], s3, m2.y);
                    sc = sn;
                }
#pragma unroll
                for (int j = W - 8; j < W; j++) {
                    ulonglong2 m2 = b[j & 7];
                    if (an)
                        b[j & 7] = __ldg(mbase +
                            (size_t)(I + W + (j - (W - 8))) * (NN / 4) + cg);
                    float4 sn;
                    if (j < W - 1) sn = sp4[j + 1];
                    unsigned long long s0 = dup_(sc.x), s1 = dup_(sc.y);
                    unsigned long long s2 = dup_(sc.z), s3 = dup_(sc.w);
                    fma2_(A[0], s0, m2.x); fma2_(A[1], s0, m2.y);
                    fma2_(A[2], s1, m2.x); fma2_(A[3], s1, m2.y);
                    fma2_(A[4], s2, m2.x); fma2_(A[5], s2, m2.y);
                    fma2_(A[6], s3, m2.x); fma2_(A[7], s3, m2.y);
                    if (j < W - 1) sc = sn;
                }
            }
            // publish diag acc base for S(it+1) to BOTH CTAs (8 threads/CTA)
            if (it + 1 < NB) {
                const int cd0 = (it + 1) * 16;
                if (cg >= cd0 && cg < cd0 + 16) {
                    const int off = (cg - cd0) * 4;
                    const int p2 = par ^ 1;
#pragma unroll
                    for (int g = 0; g < G; g++) {
                        unsigned long long* dst =
                            (unsigned long long*)&sm->dbase[p2][g][off];
                        dst[0] = A[2 * g]; dst[1] = A[2 * g + 1];
                        unsigned la = smem_u32(dst);
                        st_peer64(la, rank ^ 1u, A[2 * g]);
                        st_peer64(la + 8, rank ^ 1u, A[2 * g + 1]);
                    }
                }
            }
        }

        cluster_arrive_();

        // ---- stage block it+1, vectorized: 4 LDG.128 batched, then 4 STS.128
        if (it + 1 < NB) {
            const int I2 = (it + 1) * W;
            const int p2 = par ^ 1;
            if (tid < NSEQ) {
                int g = tid >> 5;
                sm->thrS[p2][g][lane] =
                    __ldg(g_thrA + (size_t)(bb + g) * NN + I2 + lane);
                sm->thrS[p2][g][lane + 32] =
                    __ldg(g_thrA + (size_t)(bb + g) * NN + I2 + lane + 32);
            } else {
                // thread bt owns float4 indices f0=2bt, f1=2bt+1 of the 64x64
                // tiles (1024 float4 each); rr = f>>4, cc = (f&15)*4
                const int f0 = 2 * bt, f1 = 2 * bt + 1;
                const int r0 = f0 >> 4, c0 = (f0 & 15) * 4;
                const int r1 = f1 >> 4, c1 = (f1 & 15) * 4;
                float4 d0 = __ldg((const float4*)(g_maskT + (size_t)(I2 + r0) * NN + I2 + c0));
                float4 d1 = __ldg((const float4*)(g_maskT + (size_t)(I2 + r1) * NN + I2 + c1));
                float4 e0 = __ldg((const float4*)(g_maskT + (size_t)(I2 - W + r0) * NN + I2 + c0));
                float4 e1 = __ldg((const float4*)(g_maskT + (size_t)(I2 - W + r1) * NN + I2 + c1));
                *(float4*)&sm->ds[p2][r0][c0] = d0;
                *(float4*)&sm->ds[p2][r1][c1] = d1;
                *(float4*)&sm->es[p2][r0][c0] = e0;
                *(float4*)&sm->es[p2][r1][c1] = e1;
            }
        }
    }
    cluster_wait_();

    // ---- x_hat epilogue: row N-1 of maskT is all-zero, so A == acc_prev ----
    if (tid >= NSEQ) {
        float* xh = out + (size_t)BB * NN;
        float4 wv = __ldg((const float4*)weight + cg);
#pragma unroll
        for (int g = 0; g < G; g++) {
            float a0 = __uint_as_float((unsigned)(A[2 * g] & 0xffffffffu));
            float a1 = __uint_as_float((unsigned)(A[2 * g] >> 32));
            float a2 = __uint_as_float((unsigned)(A[2 * g + 1] & 0xffffffffu));
            float a3 = __uint_as_float((unsigned)(A[2 * g + 1] >> 32));
            float4 r;
            r.x = xla_sigmoid(__fmul_rn(wv.x, a0));
            r.y = xla_sigmoid(__fmul_rn(wv.y, a1));
            r.z = xla_sigmoid(__fmul_rn(wv.z, a2));
            r.w = xla_sigmoid(__fmul_rn(wv.w, a3));
            *(float4*)(xh + (size_t)(bb + g) * NN + 4 * cg) = r;
        }
    }
    __syncthreads();
    cluster_arrive_();
    cluster_wait_();
}

extern "C" void kernel_launch(void* const* d_in, const int* in_sizes, int n_in,
                              void* d_out, int out_size)
{
    const float* weight = (const float*)d_in[0]; // [N]
    const float* mask   = (const float*)d_in[1]; // [N,N] row-major
    const float* u      = (const float*)d_in[2]; // [B,N]
    float* out = (float*)d_out;                  // [2*B*N]: sample then x_hat

    // raise dynamic smem cap (not a stream op; capture-safe, idempotent)
    cudaFuncSetAttribute(hot_kernel,
                         cudaFuncAttributeMaxDynamicSharedMemorySize,
                         (int)sizeof(Smem));

    dim3 tb(32, 8), tg(NN / 32, NN / 32);
    transpose_kernel<<<tg, tb>>>(mask);
    thr_kernel<<<(BB * NN + 255) / 256, 256>>>(u, weight);
    nop_kernel<<<1, 32>>>();   // shifts ncu capture slot onto hot_kernel
    hot_kernel<<<NCTA, T, sizeof(Smem)>>>(weight, out);
    (void)in_sizes; (void)n_in; (void)out_size;
}